// round 4
// baseline (speedup 1.0000x reference)
#include <cuda_runtime.h>
#include <cuda_bf16.h>
#include <stdint.h>
#include <math.h>

#define T_TOK 8192
#define TT    16384          // 2*T gathered rows
#define D_DIM 1024
#define H_DIM 684
#define HP    704            // H padded to multiple of 64
#define NE    8
#define KA1   2048           // [hi | lo] physical width for D-side operands
#define KA2   1408           // [hi | lo] physical width for H-side operands
#define NC1   96             // logical K chunks (3*1024/32)
#define NC2   66             // logical K chunks (3*704/32)

// ======================= scratch =======================
__device__ __nv_bfloat16 xg2[(size_t)TT * KA1];
__device__ __nv_bfloat16 w1c[(size_t)NE * H_DIM * KA1];
__device__ __nv_bfloat16 w3c[(size_t)NE * H_DIM * KA1];
__device__ __nv_bfloat16 w2c[(size_t)NE * D_DIM * KA2];
__device__ __nv_bfloat16 h2_[(size_t)TT * KA2];
__device__ float g_y[(size_t)TT * D_DIM];

__device__ int   g_rows[TT];
__device__ int   g_pos[TT];
__device__ int   g_cnt[NE];
__device__ int   g_off[NE];
__device__ int   g_cur[NE];
__device__ int   g_top[TT];
__device__ float g_topp[TT];
__device__ int   g_dcnt[NE];
__device__ float g_psum[NE];

// ======================= asm helpers (portable sm_80+) =======================
__device__ __forceinline__ uint32_t smem_to_u32(const void* p) {
    uint32_t a;
    asm("{ .reg .u64 t; cvta.to.shared.u64 t, %1; cvt.u32.u64 %0, t; }" : "=r"(a) : "l"(p));
    return a;
}

__device__ __forceinline__ void cp16(uint32_t dst, const void* src) {
    asm volatile("cp.async.cg.shared.global [%0], [%1], 16;" :: "r"(dst), "l"(src) : "memory");
}
#define CP_COMMIT() asm volatile("cp.async.commit_group;" ::: "memory")
#define CP_WAIT1()  asm volatile("cp.async.wait_group 1;" ::: "memory")

__device__ __forceinline__ void ldsm4(uint32_t* r, uint32_t addr) {
    asm volatile("ldmatrix.sync.aligned.m8n8.x4.shared.b16 {%0,%1,%2,%3}, [%4];"
                 : "=r"(r[0]), "=r"(r[1]), "=r"(r[2]), "=r"(r[3]) : "r"(addr));
}

__device__ __forceinline__ void mma16816(float* c, const uint32_t* a, uint32_t b0, uint32_t b1) {
    asm volatile("mma.sync.aligned.m16n8k16.row.col.f32.bf16.bf16.f32 "
                 "{%0,%1,%2,%3}, {%4,%5,%6,%7}, {%8,%9}, {%0,%1,%2,%3};"
                 : "+f"(c[0]), "+f"(c[1]), "+f"(c[2]), "+f"(c[3])
                 : "r"(a[0]), "r"(a[1]), "r"(a[2]), "r"(a[3]), "r"(b0), "r"(b1));
}

// ======================= small kernels =======================
__global__ void k_init0() {
    int i = threadIdx.x;
    if (i < NE) { g_cnt[i] = 0; g_dcnt[i] = 0; g_psum[i] = 0.f; }
}

__global__ void k_router(const float* __restrict__ x, const float* __restrict__ rw) {
    __shared__ float s_ps[NE];
    __shared__ int   s_dc[NE];
    __shared__ int   s_cnt[NE];
    int tid = threadIdx.x;
    if (tid < NE) { s_ps[tid] = 0.f; s_dc[tid] = 0; s_cnt[tid] = 0; }
    __syncthreads();

    int warp = tid >> 5, lane = tid & 31;
    int t = blockIdx.x * 8 + warp;

    float xv[32];
    const float* xr = x + (size_t)t * D_DIM;
#pragma unroll
    for (int i = 0; i < 32; i++) xv[i] = xr[lane + 32 * i];

    float logit[NE];
#pragma unroll
    for (int e = 0; e < NE; e++) {
        const float* wr = rw + e * D_DIM;
        float s = 0.f;
#pragma unroll
        for (int i = 0; i < 32; i++) s += xv[i] * wr[lane + 32 * i];
#pragma unroll
        for (int o = 16; o; o >>= 1) s += __shfl_xor_sync(0xffffffffu, s, o);
        logit[e] = s;
    }

    if (lane == 0) {
        float mx = logit[0];
#pragma unroll
        for (int e = 1; e < NE; e++) mx = fmaxf(mx, logit[e]);
        float p[NE], sum = 0.f;
#pragma unroll
        for (int e = 0; e < NE; e++) { p[e] = expf(logit[e] - mx); sum += p[e]; }
        float inv = 1.f / sum;
#pragma unroll
        for (int e = 0; e < NE; e++) p[e] *= inv;

        int i0 = 0;
#pragma unroll
        for (int e = 1; e < NE; e++) if (p[e] > p[i0]) i0 = e;
        int i1 = (i0 == 0) ? 1 : 0;
#pragma unroll
        for (int e = 0; e < NE; e++) if (e != i0 && p[e] > p[i1]) i1 = e;

        g_top[t * 2]      = i0;    g_top[t * 2 + 1]  = i1;
        g_topp[t * 2]     = p[i0]; g_topp[t * 2 + 1] = p[i1];

        atomicAdd(&s_dc[i0], 1);
        atomicAdd(&s_cnt[i0], 1);
        atomicAdd(&s_cnt[i1], 1);
#pragma unroll
        for (int e = 0; e < NE; e++) atomicAdd(&s_ps[e], p[e]);
    }
    __syncthreads();
    if (tid < NE) {
        atomicAdd(&g_psum[tid], s_ps[tid]);
        atomicAdd(&g_dcnt[tid], s_dc[tid]);
        atomicAdd(&g_cnt[tid], s_cnt[tid]);
    }
}

__global__ void k_scan(float* out, int out_size) {
    int o = 0;
    for (int e = 0; e < NE; e++) { g_off[e] = o; g_cur[e] = o; o += g_cnt[e]; }
    float s = 0.f;
    for (int e = 0; e < NE; e++)
        s += ((float)g_dcnt[e] / (float)T_TOK) * (g_psum[e] / (float)T_TOK);
    float aux = 0.01f * s * (float)NE;
    if (out_size > T_TOK * D_DIM) out[T_TOK * D_DIM] = aux;
}

__global__ void k_scatter() {
    int i = blockIdx.x * blockDim.x + threadIdx.x;
    if (i >= TT) return;
    int e = g_top[i];
    int pos = atomicAdd(&g_cur[e], 1);
    g_rows[pos] = i >> 1;
    g_pos[i] = pos;
}

// ---- bf16 hi/lo split ----
__device__ __forceinline__ void bsplit(float v, __nv_bfloat16& h, __nv_bfloat16& l) {
    h = __float2bfloat16(v);
    l = __float2bfloat16(v - __bfloat162float(h));
}
// hi at base+o, lo at base+o+seg
__device__ __forceinline__ void store4_2seg(__nv_bfloat16* base, size_t o, size_t seg, float4 v) {
    __nv_bfloat16 h0,l0,h1,l1,h2,l2,h3,l3;
    bsplit(v.x,h0,l0); bsplit(v.y,h1,l1); bsplit(v.z,h2,l2); bsplit(v.w,h3,l3);
    __nv_bfloat162 ha; ha.x=h0; ha.y=h1;
    __nv_bfloat162 hb; hb.x=h2; hb.y=h3;
    __nv_bfloat162 la; la.x=l0; la.y=l1;
    __nv_bfloat162 lb; lb.x=l2; lb.y=l3;
    *reinterpret_cast<__nv_bfloat162*>(base + o)           = ha;
    *reinterpret_cast<__nv_bfloat162*>(base + o + 2)       = hb;
    *reinterpret_cast<__nv_bfloat162*>(base + o + seg)     = la;
    *reinterpret_cast<__nv_bfloat162*>(base + o + seg + 2) = lb;
}

// w1,w3: [NE*H][1024] -> [NE*H][2048] ([hi|lo])
__global__ void k_conv13(const float* __restrict__ w1, const float* __restrict__ w3) {
    size_t i = (size_t)blockIdx.x * 256 + threadIdx.x;
    size_t row = i >> 8;
    size_t col = (i & 255) * 4;
    float4 a = reinterpret_cast<const float4*>(w1)[i];
    float4 b = reinterpret_cast<const float4*>(w3)[i];
    store4_2seg(w1c, row * KA1 + col, D_DIM, a);
    store4_2seg(w3c, row * KA1 + col, D_DIM, b);
}

// w2: [NE*D][684] -> [NE*D][1408]  ([hi|lo], K padded to 704)
__global__ void k_conv2(const float* __restrict__ w2) {
    size_t i = (size_t)blockIdx.x * 256 + threadIdx.x;     // over [NE*D][176] float4s
    size_t row = i / 176;
    int col = (int)(i % 176) * 4;
    float4 v = make_float4(0.f, 0.f, 0.f, 0.f);
    if (col < H_DIM) {
        const float* p = w2 + row * H_DIM + col;
        v.x = p[0];
        v.y = (col + 1 < H_DIM) ? p[1] : 0.f;
        v.z = (col + 2 < H_DIM) ? p[2] : 0.f;
        v.w = (col + 3 < H_DIM) ? p[3] : 0.f;
    }
    store4_2seg(w2c, row * KA2 + (size_t)col, HP, v);
}

// gather x rows -> xg2 [hi | lo]
__global__ void k_gather(const float* __restrict__ x) {
    int p = blockIdx.x, c = threadIdx.x;
    int tok = g_rows[p];
    float4 v = reinterpret_cast<const float4*>(x)[(size_t)tok * 256 + c];
    store4_2seg(xg2, (size_t)p * KA1 + (size_t)c * 4, D_DIM, v);
}

__global__ void k_combine(float* __restrict__ out) {
    int i = blockIdx.x * 256 + threadIdx.x;
    int t = i >> 8, c = i & 255;
    int p0 = g_pos[2 * t], p1 = g_pos[2 * t + 1];
    float c0 = g_topp[2 * t], c1 = g_topp[2 * t + 1];
    const float4* y = reinterpret_cast<const float4*>(g_y);
    float4 a = y[(size_t)p0 * 256 + c];
    float4 b = y[(size_t)p1 * 256 + c];
    float4 o;
    o.x = c0 * a.x + c1 * b.x;  o.y = c0 * a.y + c1 * b.y;
    o.z = c0 * a.z + c1 * b.z;  o.w = c0 * a.w + c1 * b.w;
    reinterpret_cast<float4*>(out)[(size_t)t * 256 + c] = o;
}

// ======================= GEMM cores =======================
#define TILE_B   10240     // 128 rows * 80B
#define RSTRIDE  80

// logical chunk c -> physical K offsets in 2-seg buffers
// A logical [hi, lo, hi]; B logical [hi, hi, lo]
__device__ __forceinline__ int aoff1(int c) { return ((c >= 64) ? c - 64 : c) * 32; }
__device__ __forceinline__ int boff1(int c) { return ((c >= 32) ? c - 32 : c) * 32; }
__device__ __forceinline__ int aoff2(int c) { return ((c >= 44) ? c - 44 : c) * 32; }
__device__ __forceinline__ int boff2(int c) { return ((c >= 22) ? c - 22 : c) * 32; }

__device__ __forceinline__ void compute_warp(
    uint32_t sB, const uint32_t a[2][2][4],
    float acc[2][4][4], int warp_n0, int lane)
{
#pragma unroll
    for (int nj2 = 0; nj2 < 2; nj2++) {
#pragma unroll
        for (int kh = 0; kh < 2; kh++) {
            uint32_t r[4];
            uint32_t bd = sB + (warp_n0 + nj2*16 + (lane & 15)) * RSTRIDE
                             + (kh*16 + (lane >> 4) * 8) * 2;
            ldsm4(r, bd);
            mma16816(acc[0][nj2*2 + 0], a[0][kh], r[0], r[2]);
            mma16816(acc[0][nj2*2 + 1], a[0][kh], r[1], r[3]);
            mma16816(acc[1][nj2*2 + 0], a[1][kh], r[0], r[2]);
            mma16816(acc[1][nj2*2 + 1], a[1][kh], r[1], r[3]);
        }
    }
}

__device__ __forceinline__ void load_a_frags(
    uint32_t sA, uint32_t a[2][2][4], int warp_m0, int lane)
{
#pragma unroll
    for (int mi = 0; mi < 2; mi++)
#pragma unroll
        for (int kh = 0; kh < 2; kh++) {
            uint32_t ad = sA + (warp_m0 + mi*16 + (lane & 15)) * RSTRIDE
                             + (kh*16 + (lane >> 4) * 8) * 2;
            ldsm4(a[mi][kh], ad);
        }
}

// ------- GEMM1: 128x128 CTA, dual accum (w1,w3), SwiGLU epilogue -------
__global__ __launch_bounds__(512, 1) void k_gemm1() {
    extern __shared__ char smem[];
    const int e = blockIdx.z;
    const int cnt = g_cnt[e];
    const int m0 = blockIdx.x * 128;
    if (m0 >= cnt) return;
    const int base = g_off[e];
    const int n0g = blockIdx.y * 128;
    const int tid = threadIdx.x, wid = tid >> 5, lane = tid & 31;
    const int warp_m0 = (wid >> 2) * 32, warp_n0 = (wid & 3) * 32;

    uint32_t sb = smem_to_u32(smem);
    const __nv_bfloat16* B1 = w1c + (size_t)e * H_DIM * KA1;
    const __nv_bfloat16* B3 = w3c + (size_t)e * H_DIM * KA1;
    const long arow = base + m0;
    const int lrow = tid >> 2, lch = tid & 3;

    long ar = arow + lrow; if (ar >= TT) ar = TT - 1;
    int nr = n0g + lrow;  if (nr > H_DIM - 1) nr = H_DIM - 1;
    const __nv_bfloat16* gA  = xg2 + ar * (long)KA1 + lch * 8;
    const __nv_bfloat16* gB1 = B1 + (long)nr * KA1 + lch * 8;
    const __nv_bfloat16* gB3 = B3 + (long)nr * KA1 + lch * 8;
    const uint32_t sdst = sb + lrow * RSTRIDE + lch * 16;

    auto load_stage = [&](int st, int c) {
        uint32_t d = sdst + st * (3 * TILE_B);
        cp16(d,            gA  + aoff1(c));
        cp16(d + TILE_B,   gB1 + boff1(c));
        cp16(d + 2*TILE_B, gB3 + boff1(c));
    };

    float acc1[2][4][4] = {{{0}}}, acc3[2][4][4] = {{{0}}};

    load_stage(0, 0); CP_COMMIT();
    load_stage(1, 1); CP_COMMIT();

    for (int c = 0; c < NC1; c++) {
        CP_WAIT1();
        __syncthreads();
        if (c + 2 < NC1) load_stage((c + 2) % 3, c + 2);
        CP_COMMIT();
        uint32_t sA = sb + (c % 3) * (3 * TILE_B);
        uint32_t a[2][2][4];
        load_a_frags(sA, a, warp_m0, lane);
        compute_warp(sA + TILE_B,   a, acc1, warp_n0, lane);
        compute_warp(sA + 2*TILE_B, a, acc3, warp_n0, lane);
    }

    // epilogue: swiglu + split into h2 [hi | lo]
#pragma unroll
    for (int mi = 0; mi < 2; mi++) {
#pragma unroll
        for (int nj = 0; nj < 4; nj++) {
            int n = n0g + warp_n0 + nj * 8 + ((lane & 3) << 1);
            if (n >= HP) continue;
            bool live = (n < H_DIM);
#pragma unroll
            for (int h = 0; h < 2; h++) {
                int rl = warp_m0 + mi * 16 + (lane >> 2) + h * 8;
                int r = m0 + rl;
                if (r >= cnt) continue;
                float v1a = acc1[mi][nj][2*h],   v3a = acc3[mi][nj][2*h];
                float v1b = acc1[mi][nj][2*h+1], v3b = acc3[mi][nj][2*h+1];
                float ha = live ? (v1a / (1.f + __expf(-v1a))) * v3a : 0.f;
                float hb = live ? (v1b / (1.f + __expf(-v1b))) * v3b : 0.f;
                __nv_bfloat16 hah, hal, hbh, hbl;
                bsplit(ha, hah, hal); bsplit(hb, hbh, hbl);
                __nv_bfloat162 hv; hv.x = hah; hv.y = hbh;
                __nv_bfloat162 lv; lv.x = hal; lv.y = hbl;
                size_t rb = (size_t)(base + r) * KA2;
                *reinterpret_cast<__nv_bfloat162*>(h2_ + rb + n)      = hv;
                *reinterpret_cast<__nv_bfloat162*>(h2_ + rb + HP + n) = lv;
            }
        }
    }
}

// ------- GEMM2: 256x128 CTA, warp tile 64x32, y = h2 @ w2c^T -------
__global__ __launch_bounds__(512, 1) void k_gemm2() {
    extern __shared__ char smem[];
    const int e = blockIdx.z;
    const int cnt = g_cnt[e];
    const int m0 = blockIdx.x * 256;
    if (m0 >= cnt) return;
    const int base = g_off[e];
    const int n0g = blockIdx.y * 128;
    const int tid = threadIdx.x, wid = tid >> 5, lane = tid & 31;
    const int warp_m0 = (wid >> 2) * 64, warp_n0 = (wid & 3) * 32;

    uint32_t sb = smem_to_u32(smem);
    const __nv_bfloat16* B = w2c + (size_t)e * D_DIM * KA2;
    const long arow = base + m0;
    const int lrow = tid >> 2, lch = tid & 3;       // 128 rows x 4 chunks

    long ar0 = arow + lrow;        if (ar0 >= TT) ar0 = TT - 1;
    long ar1 = arow + lrow + 128;  if (ar1 >= TT) ar1 = TT - 1;
    int nr = n0g + lrow;                             // < 1024 always
    const __nv_bfloat16* gA0 = h2_ + ar0 * (long)KA2 + lch * 8;
    const __nv_bfloat16* gA1 = h2_ + ar1 * (long)KA2 + lch * 8;
    const __nv_bfloat16* gB  = B + (long)nr * KA2 + lch * 8;
    const uint32_t sdst = sb + lrow * RSTRIDE + lch * 16;

    const int STAGE = 3 * TILE_B;                    // 20480 A + 10240 B
    auto load_stage = [&](int st, int c) {
        uint32_t d = sdst + st * STAGE;
        int ao = aoff2(c), bo = boff2(c);
        cp16(d,                  gA0 + ao);
        cp16(d + 128 * RSTRIDE,  gA1 + ao);
        cp16(d + 2 * TILE_B,     gB  + bo);
    };

    float acc[4][4][4] = {{{0}}};

    load_stage(0, 0); CP_COMMIT();
    load_stage(1, 1); CP_COMMIT();

    for (int c = 0; c < NC2; c++) {
        CP_WAIT1();
        __syncthreads();
        if (c + 2 < NC2) load_stage((c + 2) % 3, c + 2);
        CP_COMMIT();
        uint32_t sA = sb + (c % 3) * STAGE;
        uint32_t sB = sA + 2 * TILE_B;
#pragma unroll
        for (int kh = 0; kh < 2; kh++) {
            uint32_t a[4][4];
#pragma unroll
            for (int mi = 0; mi < 4; mi++) {
                uint32_t ad = sA + (warp_m0 + mi*16 + (lane & 15)) * RSTRIDE
                                 + (kh*16 + (lane >> 4) * 8) * 2;
                ldsm4(a[mi], ad);
            }
#pragma unroll
            for (int nj2 = 0; nj2 < 2; nj2++) {
                uint32_t r[4];
                uint32_t bd = sB + (warp_n0 + nj2*16 + (lane & 15)) * RSTRIDE
                                 + (kh*16 + (lane >> 4) * 8) * 2;
                ldsm4(r, bd);
#pragma unroll
                for (int mi = 0; mi < 4; mi++) {
                    mma16816(acc[mi][nj2*2 + 0], a[mi], r[0], r[2]);
                    mma16816(acc[mi][nj2*2 + 1], a[mi], r[1], r[3]);
                }
            }
        }
    }

#pragma unroll
    for (int mi = 0; mi < 4; mi++) {
#pragma unroll
        for (int nj = 0; nj < 4; nj++) {
            int n = n0g + warp_n0 + nj * 8 + ((lane & 3) << 1);
#pragma unroll
            for (int h = 0; h < 2; h++) {
                int rl = warp_m0 + mi * 16 + (lane >> 2) + h * 8;
                int r = m0 + rl;
                if (r >= cnt) continue;
                float2 v; v.x = acc[mi][nj][2*h]; v.y = acc[mi][nj][2*h+1];
                *reinterpret_cast<float2*>(g_y + (size_t)(base + r) * D_DIM + n) = v;
            }
        }
    }
}

// ======================= launch =======================
extern "C" void kernel_launch(void* const* d_in, const int* in_sizes, int n_in,
                              void* d_out, int out_size) {
    const float* x  = (const float*)d_in[0];
    const float* rw = (const float*)d_in[1];
    const float* w1 = (const float*)d_in[2];
    const float* w2 = (const float*)d_in[3];
    const float* w3 = (const float*)d_in[4];
    float* out = (float*)d_out;

    cudaFuncSetAttribute(k_gemm1, cudaFuncAttributeMaxDynamicSharedMemorySize, 3 * 3 * TILE_B);
    cudaFuncSetAttribute(k_gemm2, cudaFuncAttributeMaxDynamicSharedMemorySize, 3 * 3 * TILE_B);

    k_init0<<<1, 32>>>();
    k_router<<<T_TOK / 8, 256>>>(x, rw);
    k_scan<<<1, 1>>>(out, out_size);
    k_scatter<<<TT / 256, 256>>>();

    k_conv13<<<NE * H_DIM, 256>>>(w1, w3);
    k_conv2<<<NE * D_DIM * 176 / 256, 256>>>(w2);
    k_gather<<<TT, 256>>>(x);

    k_gemm1<<<dim3(64, 6, 8), 512, 3 * 3 * TILE_B>>>();
    k_gemm2<<<dim3(32, 8, 8), 512, 3 * 3 * TILE_B>>>();
    k_combine<<<T_TOK, 256>>>(out);
}

// round 5
// speedup vs baseline: 1.0934x; 1.0934x over previous
#include <cuda_runtime.h>
#include <cuda_bf16.h>
#include <stdint.h>
#include <math.h>

#define T_TOK 8192
#define TT    16384          // 2*T gathered rows
#define D_DIM 1024
#define H_DIM 684
#define HP    704            // H padded to multiple of 64
#define NE    8
#define KA1   2048           // [hi | lo] physical width for D-side operands
#define KA2   1408           // [hi | lo] physical width for H-side operands
#define NCH1  32             // physical K chunks (1024/32)
#define NCH2  22             // physical K chunks (704/32)

// ======================= scratch =======================
__device__ __nv_bfloat16 xg2[(size_t)TT * KA1];
__device__ __nv_bfloat16 w1c[(size_t)NE * H_DIM * KA1];
__device__ __nv_bfloat16 w3c[(size_t)NE * H_DIM * KA1];
__device__ __nv_bfloat16 w2c[(size_t)NE * D_DIM * KA2];
__device__ __nv_bfloat16 h2_[(size_t)TT * KA2];
__device__ float g_y[(size_t)TT * D_DIM];

__device__ int   g_rows[TT];
__device__ int   g_pos[TT];
__device__ int   g_cnt[NE];
__device__ int   g_off[NE];
__device__ int   g_cur[NE];
__device__ int   g_top[TT];
__device__ float g_topp[TT];
__device__ int   g_dcnt[NE];
__device__ float g_psum[NE];

// ======================= asm helpers (portable sm_80+) =======================
__device__ __forceinline__ uint32_t smem_to_u32(const void* p) {
    uint32_t a;
    asm("{ .reg .u64 t; cvta.to.shared.u64 t, %1; cvt.u32.u64 %0, t; }" : "=r"(a) : "l"(p));
    return a;
}

__device__ __forceinline__ void cp16(uint32_t dst, const void* src) {
    asm volatile("cp.async.cg.shared.global [%0], [%1], 16;" :: "r"(dst), "l"(src) : "memory");
}
#define CP_COMMIT() asm volatile("cp.async.commit_group;" ::: "memory")
#define CP_WAIT1()  asm volatile("cp.async.wait_group 1;" ::: "memory")

__device__ __forceinline__ void ldsm4(uint32_t* r, uint32_t addr) {
    asm volatile("ldmatrix.sync.aligned.m8n8.x4.shared.b16 {%0,%1,%2,%3}, [%4];"
                 : "=r"(r[0]), "=r"(r[1]), "=r"(r[2]), "=r"(r[3]) : "r"(addr));
}

__device__ __forceinline__ void mma16816(float* c, const uint32_t* a, uint32_t b0, uint32_t b1) {
    asm volatile("mma.sync.aligned.m16n8k16.row.col.f32.bf16.bf16.f32 "
                 "{%0,%1,%2,%3}, {%4,%5,%6,%7}, {%8,%9}, {%0,%1,%2,%3};"
                 : "+f"(c[0]), "+f"(c[1]), "+f"(c[2]), "+f"(c[3])
                 : "r"(a[0]), "r"(a[1]), "r"(a[2]), "r"(a[3]), "r"(b0), "r"(b1));
}

// ======================= small kernels =======================
__global__ void k_init0() {
    int i = threadIdx.x;
    if (i < NE) { g_cnt[i] = 0; g_dcnt[i] = 0; g_psum[i] = 0.f; }
}

__global__ void k_router(const float* __restrict__ x, const float* __restrict__ rw) {
    __shared__ float s_ps[NE];
    __shared__ int   s_dc[NE];
    __shared__ int   s_cnt[NE];
    int tid = threadIdx.x;
    if (tid < NE) { s_ps[tid] = 0.f; s_dc[tid] = 0; s_cnt[tid] = 0; }
    __syncthreads();

    int warp = tid >> 5, lane = tid & 31;
    int t = blockIdx.x * 8 + warp;

    float xv[32];
    const float* xr = x + (size_t)t * D_DIM;
#pragma unroll
    for (int i = 0; i < 32; i++) xv[i] = xr[lane + 32 * i];

    float logit[NE];
#pragma unroll
    for (int e = 0; e < NE; e++) {
        const float* wr = rw + e * D_DIM;
        float s = 0.f;
#pragma unroll
        for (int i = 0; i < 32; i++) s += xv[i] * wr[lane + 32 * i];
#pragma unroll
        for (int o = 16; o; o >>= 1) s += __shfl_xor_sync(0xffffffffu, s, o);
        logit[e] = s;
    }

    if (lane == 0) {
        float mx = logit[0];
#pragma unroll
        for (int e = 1; e < NE; e++) mx = fmaxf(mx, logit[e]);
        float p[NE], sum = 0.f;
#pragma unroll
        for (int e = 0; e < NE; e++) { p[e] = expf(logit[e] - mx); sum += p[e]; }
        float inv = 1.f / sum;
#pragma unroll
        for (int e = 0; e < NE; e++) p[e] *= inv;

        int i0 = 0;
#pragma unroll
        for (int e = 1; e < NE; e++) if (p[e] > p[i0]) i0 = e;
        int i1 = (i0 == 0) ? 1 : 0;
#pragma unroll
        for (int e = 0; e < NE; e++) if (e != i0 && p[e] > p[i1]) i1 = e;

        g_top[t * 2]      = i0;    g_top[t * 2 + 1]  = i1;
        g_topp[t * 2]     = p[i0]; g_topp[t * 2 + 1] = p[i1];

        atomicAdd(&s_dc[i0], 1);
        atomicAdd(&s_cnt[i0], 1);
        atomicAdd(&s_cnt[i1], 1);
#pragma unroll
        for (int e = 0; e < NE; e++) atomicAdd(&s_ps[e], p[e]);
    }
    __syncthreads();
    if (tid < NE) {
        atomicAdd(&g_psum[tid], s_ps[tid]);
        atomicAdd(&g_dcnt[tid], s_dc[tid]);
        atomicAdd(&g_cnt[tid], s_cnt[tid]);
    }
}

__global__ void k_scan(float* out, int out_size) {
    int o = 0;
    for (int e = 0; e < NE; e++) { g_off[e] = o; g_cur[e] = o; o += g_cnt[e]; }
    float s = 0.f;
    for (int e = 0; e < NE; e++)
        s += ((float)g_dcnt[e] / (float)T_TOK) * (g_psum[e] / (float)T_TOK);
    float aux = 0.01f * s * (float)NE;
    if (out_size > T_TOK * D_DIM) out[T_TOK * D_DIM] = aux;
}

__global__ void k_scatter() {
    int i = blockIdx.x * blockDim.x + threadIdx.x;
    if (i >= TT) return;
    int e = g_top[i];
    int pos = atomicAdd(&g_cur[e], 1);
    g_rows[pos] = i >> 1;
    g_pos[i] = pos;
}

// ---- bf16 hi/lo split ----
__device__ __forceinline__ void bsplit(float v, __nv_bfloat16& h, __nv_bfloat16& l) {
    h = __float2bfloat16(v);
    l = __float2bfloat16(v - __bfloat162float(h));
}
__device__ __forceinline__ void store4_2seg(__nv_bfloat16* base, size_t o, size_t seg, float4 v) {
    __nv_bfloat16 h0,l0,h1,l1,h2,l2,h3,l3;
    bsplit(v.x,h0,l0); bsplit(v.y,h1,l1); bsplit(v.z,h2,l2); bsplit(v.w,h3,l3);
    __nv_bfloat162 ha; ha.x=h0; ha.y=h1;
    __nv_bfloat162 hb; hb.x=h2; hb.y=h3;
    __nv_bfloat162 la; la.x=l0; la.y=l1;
    __nv_bfloat162 lb; lb.x=l2; lb.y=l3;
    *reinterpret_cast<__nv_bfloat162*>(base + o)           = ha;
    *reinterpret_cast<__nv_bfloat162*>(base + o + 2)       = hb;
    *reinterpret_cast<__nv_bfloat162*>(base + o + seg)     = la;
    *reinterpret_cast<__nv_bfloat162*>(base + o + seg + 2) = lb;
}

__global__ void k_conv13(const float* __restrict__ w1, const float* __restrict__ w3) {
    size_t i = (size_t)blockIdx.x * 256 + threadIdx.x;
    size_t row = i >> 8;
    size_t col = (i & 255) * 4;
    float4 a = reinterpret_cast<const float4*>(w1)[i];
    float4 b = reinterpret_cast<const float4*>(w3)[i];
    store4_2seg(w1c, row * KA1 + col, D_DIM, a);
    store4_2seg(w3c, row * KA1 + col, D_DIM, b);
}

__global__ void k_conv2(const float* __restrict__ w2) {
    size_t i = (size_t)blockIdx.x * 256 + threadIdx.x;     // over [NE*D][176] float4s
    size_t row = i / 176;
    int col = (int)(i % 176) * 4;
    float4 v = make_float4(0.f, 0.f, 0.f, 0.f);
    if (col < H_DIM) {
        const float* p = w2 + row * H_DIM + col;
        v.x = p[0];
        v.y = (col + 1 < H_DIM) ? p[1] : 0.f;
        v.z = (col + 2 < H_DIM) ? p[2] : 0.f;
        v.w = (col + 3 < H_DIM) ? p[3] : 0.f;
    }
    store4_2seg(w2c, row * KA2 + (size_t)col, HP, v);
}

__global__ void k_gather(const float* __restrict__ x) {
    int p = blockIdx.x, c = threadIdx.x;
    int tok = g_rows[p];
    float4 v = reinterpret_cast<const float4*>(x)[(size_t)tok * 256 + c];
    store4_2seg(xg2, (size_t)p * KA1 + (size_t)c * 4, D_DIM, v);
}

__global__ void k_combine(float* __restrict__ out) {
    int i = blockIdx.x * 256 + threadIdx.x;
    int t = i >> 8, c = i & 255;
    int p0 = g_pos[2 * t], p1 = g_pos[2 * t + 1];
    float c0 = g_topp[2 * t], c1 = g_topp[2 * t + 1];
    const float4* y = reinterpret_cast<const float4*>(g_y);
    float4 a = y[(size_t)p0 * 256 + c];
    float4 b = y[(size_t)p1 * 256 + c];
    float4 o;
    o.x = c0 * a.x + c1 * b.x;  o.y = c0 * a.y + c1 * b.y;
    o.z = c0 * a.z + c1 * b.z;  o.w = c0 * a.w + c1 * b.w;
    reinterpret_cast<float4*>(out)[(size_t)t * 256 + c] = o;
}

// ======================= GEMM cores =======================
#define TILE_B   10240     // 128 rows * 80B
#define RSTRIDE  80
#define STAGE1   (6 * TILE_B)   // Ah Al B1h B1l B3h B3l
#define STAGE2   (4 * TILE_B)   // Ah Al Bh Bl

__device__ __forceinline__ void compute_warp(
    uint32_t sB, const uint32_t a[2][2][4],
    float acc[2][4][4], int warp_n0, int lane)
{
#pragma unroll
    for (int nj2 = 0; nj2 < 2; nj2++) {
#pragma unroll
        for (int kh = 0; kh < 2; kh++) {
            uint32_t r[4];
            uint32_t bd = sB + (warp_n0 + nj2*16 + (lane & 15)) * RSTRIDE
                             + (kh*16 + (lane >> 4) * 8) * 2;
            ldsm4(r, bd);
            mma16816(acc[0][nj2*2 + 0], a[0][kh], r[0], r[2]);
            mma16816(acc[0][nj2*2 + 1], a[0][kh], r[1], r[3]);
            mma16816(acc[1][nj2*2 + 0], a[1][kh], r[0], r[2]);
            mma16816(acc[1][nj2*2 + 1], a[1][kh], r[1], r[3]);
        }
    }
}

__device__ __forceinline__ void load_a_frags(
    uint32_t sA, uint32_t a[2][2][4], int warp_m0, int lane)
{
#pragma unroll
    for (int mi = 0; mi < 2; mi++)
#pragma unroll
        for (int kh = 0; kh < 2; kh++) {
            uint32_t ad = sA + (warp_m0 + mi*16 + (lane & 15)) * RSTRIDE
                             + (kh*16 + (lane >> 4) * 8) * 2;
            ldsm4(a[mi][kh], ad);
        }
}

// ------- GEMM1: 128x128 CTA, term-fused over physical K chunks -------
__global__ __launch_bounds__(512, 1) void k_gemm1() {
    extern __shared__ char smem[];
    const int e = blockIdx.z;
    const int cnt = g_cnt[e];
    const int m0 = blockIdx.x * 128;
    if (m0 >= cnt) return;
    const int base = g_off[e];
    const int n0g = blockIdx.y * 128;
    const int tid = threadIdx.x, wid = tid >> 5, lane = tid & 31;
    const int warp_m0 = (wid >> 2) * 32, warp_n0 = (wid & 3) * 32;

    uint32_t sb = smem_to_u32(smem);
    const __nv_bfloat16* B1 = w1c + (size_t)e * H_DIM * KA1;
    const __nv_bfloat16* B3 = w3c + (size_t)e * H_DIM * KA1;
    const long arow = base + m0;
    const int lrow = tid >> 2, lch = tid & 3;

    long ar = arow + lrow; if (ar >= TT) ar = TT - 1;
    int nr = n0g + lrow;  if (nr > H_DIM - 1) nr = H_DIM - 1;
    const __nv_bfloat16* gAh  = xg2 + ar * (long)KA1 + lch * 8;
    const __nv_bfloat16* gB1h = B1 + (long)nr * KA1 + lch * 8;
    const __nv_bfloat16* gB3h = B3 + (long)nr * KA1 + lch * 8;
    const uint32_t sdst = sb + lrow * RSTRIDE + lch * 16;

    auto load_stage = [&](int st, int kc) {
        uint32_t d = sdst + st * STAGE1;
        int ko = kc * 32;
        cp16(d,            gAh  + ko);
        cp16(d + TILE_B,   gAh  + D_DIM + ko);
        cp16(d + 2*TILE_B, gB1h + ko);
        cp16(d + 3*TILE_B, gB1h + D_DIM + ko);
        cp16(d + 4*TILE_B, gB3h + ko);
        cp16(d + 5*TILE_B, gB3h + D_DIM + ko);
    };

    float acc1[2][4][4] = {{{0}}}, acc3[2][4][4] = {{{0}}};

    load_stage(0, 0); CP_COMMIT();
    load_stage(1, 1); CP_COMMIT();

    for (int kc = 0; kc < NCH1; kc++) {
        CP_WAIT1();
        __syncthreads();
        if (kc + 2 < NCH1) load_stage((kc + 2) % 3, kc + 2);
        CP_COMMIT();
        uint32_t st = sb + (kc % 3) * STAGE1;
        uint32_t a[2][2][4];
        load_a_frags(st, a, warp_m0, lane);                 // Ah
        compute_warp(st + 2*TILE_B, a, acc1, warp_n0, lane); // Ah*B1h
        compute_warp(st + 3*TILE_B, a, acc1, warp_n0, lane); // Ah*B1l
        compute_warp(st + 4*TILE_B, a, acc3, warp_n0, lane); // Ah*B3h
        compute_warp(st + 5*TILE_B, a, acc3, warp_n0, lane); // Ah*B3l
        load_a_frags(st + TILE_B, a, warp_m0, lane);        // Al
        compute_warp(st + 2*TILE_B, a, acc1, warp_n0, lane); // Al*B1h
        compute_warp(st + 4*TILE_B, a, acc3, warp_n0, lane); // Al*B3h
    }

    // epilogue: swiglu + split into h2 [hi | lo]
#pragma unroll
    for (int mi = 0; mi < 2; mi++) {
#pragma unroll
        for (int nj = 0; nj < 4; nj++) {
            int n = n0g + warp_n0 + nj * 8 + ((lane & 3) << 1);
            if (n >= HP) continue;
            bool live = (n < H_DIM);
#pragma unroll
            for (int h = 0; h < 2; h++) {
                int rl = warp_m0 + mi * 16 + (lane >> 2) + h * 8;
                int r = m0 + rl;
                if (r >= cnt) continue;
                float v1a = acc1[mi][nj][2*h],   v3a = acc3[mi][nj][2*h];
                float v1b = acc1[mi][nj][2*h+1], v3b = acc3[mi][nj][2*h+1];
                float ha = live ? (v1a / (1.f + __expf(-v1a))) * v3a : 0.f;
                float hb = live ? (v1b / (1.f + __expf(-v1b))) * v3b : 0.f;
                __nv_bfloat16 hah, hal, hbh, hbl;
                bsplit(ha, hah, hal); bsplit(hb, hbh, hbl);
                __nv_bfloat162 hv; hv.x = hah; hv.y = hbh;
                __nv_bfloat162 lv; lv.x = hal; lv.y = hbl;
                size_t rb = (size_t)(base + r) * KA2;
                *reinterpret_cast<__nv_bfloat162*>(h2_ + rb + n)      = hv;
                *reinterpret_cast<__nv_bfloat162*>(h2_ + rb + HP + n) = lv;
            }
        }
    }
}

// ------- GEMM2: 128x128 CTA, term-fused, y = h2 @ w2c^T -------
__global__ __launch_bounds__(512, 1) void k_gemm2() {
    extern __shared__ char smem[];
    const int e = blockIdx.z;
    const int cnt = g_cnt[e];
    const int m0 = blockIdx.x * 128;
    if (m0 >= cnt) return;
    const int base = g_off[e];
    const int n0g = blockIdx.y * 128;
    const int tid = threadIdx.x, wid = tid >> 5, lane = tid & 31;
    const int warp_m0 = (wid >> 2) * 32, warp_n0 = (wid & 3) * 32;

    uint32_t sb = smem_to_u32(smem);
    const __nv_bfloat16* B = w2c + (size_t)e * D_DIM * KA2;
    const long arow = base + m0;
    const int lrow = tid >> 2, lch = tid & 3;

    long ar = arow + lrow; if (ar >= TT) ar = TT - 1;
    int nr = n0g + lrow;                       // < 1024 always
    const __nv_bfloat16* gAh = h2_ + ar * (long)KA2 + lch * 8;
    const __nv_bfloat16* gBh = B + (long)nr * KA2 + lch * 8;
    const uint32_t sdst = sb + lrow * RSTRIDE + lch * 16;

    auto load_stage = [&](int st, int kc) {
        uint32_t d = sdst + st * STAGE2;
        int ko = kc * 32;
        cp16(d,            gAh + ko);
        cp16(d + TILE_B,   gAh + HP + ko);
        cp16(d + 2*TILE_B, gBh + ko);
        cp16(d + 3*TILE_B, gBh + HP + ko);
    };

    float acc[2][4][4] = {{{0}}};

    load_stage(0, 0); CP_COMMIT();
    load_stage(1, 1); CP_COMMIT();

    for (int kc = 0; kc < NCH2; kc++) {
        CP_WAIT1();
        __syncthreads();
        if (kc + 2 < NCH2) load_stage((kc + 2) % 3, kc + 2);
        CP_COMMIT();
        uint32_t st = sb + (kc % 3) * STAGE2;
        uint32_t a[2][2][4];
        load_a_frags(st, a, warp_m0, lane);                 // Ah
        compute_warp(st + 2*TILE_B, a, acc, warp_n0, lane);  // Ah*Bh
        compute_warp(st + 3*TILE_B, a, acc, warp_n0, lane);  // Ah*Bl
        load_a_frags(st + TILE_B, a, warp_m0, lane);        // Al
        compute_warp(st + 2*TILE_B, a, acc, warp_n0, lane);  // Al*Bh
    }

#pragma unroll
    for (int mi = 0; mi < 2; mi++) {
#pragma unroll
        for (int nj = 0; nj < 4; nj++) {
            int n = n0g + warp_n0 + nj * 8 + ((lane & 3) << 1);
#pragma unroll
            for (int h = 0; h < 2; h++) {
                int rl = warp_m0 + mi * 16 + (lane >> 2) + h * 8;
                int r = m0 + rl;
                if (r >= cnt) continue;
                float2 v; v.x = acc[mi][nj][2*h]; v.y = acc[mi][nj][2*h+1];
                *reinterpret_cast<float2*>(g_y + (size_t)(base + r) * D_DIM + n) = v;
            }
        }
    }
}

// ======================= launch =======================
extern "C" void kernel_launch(void* const* d_in, const int* in_sizes, int n_in,
                              void* d_out, int out_size) {
    const float* x  = (const float*)d_in[0];
    const float* rw = (const float*)d_in[1];
    const float* w1 = (const float*)d_in[2];
    const float* w2 = (const float*)d_in[3];
    const float* w3 = (const float*)d_in[4];
    float* out = (float*)d_out;

    cudaFuncSetAttribute(k_gemm1, cudaFuncAttributeMaxDynamicSharedMemorySize, 3 * STAGE1);
    cudaFuncSetAttribute(k_gemm2, cudaFuncAttributeMaxDynamicSharedMemorySize, 3 * STAGE2);

    k_init0<<<1, 32>>>();
    k_router<<<T_TOK / 8, 256>>>(x, rw);
    k_scan<<<1, 1>>>(out, out_size);
    k_scatter<<<TT / 256, 256>>>();

    k_conv13<<<NE * H_DIM, 256>>>(w1, w3);
    k_conv2<<<NE * D_DIM * 176 / 256, 256>>>(w2);
    k_gather<<<TT, 256>>>(x);

    k_gemm1<<<dim3(128, 6, 8), 512, 3 * STAGE1>>>();
    k_gemm2<<<dim3(128, 8, 8), 512, 3 * STAGE2>>>();
    k_combine<<<T_TOK, 256>>>(out);
}

// round 6
// speedup vs baseline: 1.1222x; 1.0263x over previous
#include <cuda_runtime.h>
#include <cuda_bf16.h>
#include <stdint.h>
#include <math.h>

#define T_TOK 8192
#define TT    16384          // 2*T gathered rows
#define D_DIM 1024
#define H_DIM 684
#define HP    704            // H padded to multiple of 64
#define NE    8
#define KA1   2048           // [hi | lo] physical width for D-side operands
#define KA2   1408           // [hi | lo] physical width for H-side operands
#define NCH1  32             // physical K chunks (1024/32)
#define NCH2  22             // physical K chunks (704/32)

// ======================= scratch =======================
__device__ __nv_bfloat16 xg2[(size_t)TT * KA1];
__device__ __nv_bfloat16 w1c[(size_t)NE * H_DIM * KA1];
__device__ __nv_bfloat16 w3c[(size_t)NE * H_DIM * KA1];
__device__ __nv_bfloat16 w2c[(size_t)NE * D_DIM * KA2];
__device__ __nv_bfloat16 h2_[(size_t)TT * KA2];
__device__ float g_y[(size_t)TT * D_DIM];

__device__ int   g_pos[TT];
__device__ int   g_cnt[NE];
__device__ int   g_cur[NE];
__device__ int   g_top[TT];
__device__ float g_topp[TT];
__device__ int   g_dcnt[NE];
__device__ float g_psum[NE];

// ======================= asm helpers (portable sm_80+) =======================
__device__ __forceinline__ uint32_t smem_to_u32(const void* p) {
    uint32_t a;
    asm("{ .reg .u64 t; cvta.to.shared.u64 t, %1; cvt.u32.u64 %0, t; }" : "=r"(a) : "l"(p));
    return a;
}

__device__ __forceinline__ void cp16(uint32_t dst, const void* src) {
    asm volatile("cp.async.cg.shared.global [%0], [%1], 16;" :: "r"(dst), "l"(src) : "memory");
}
#define CP_COMMIT() asm volatile("cp.async.commit_group;" ::: "memory")
#define CP_WAIT1()  asm volatile("cp.async.wait_group 1;" ::: "memory")
#define CP_WAIT2()  asm volatile("cp.async.wait_group 2;" ::: "memory")

__device__ __forceinline__ void ldsm4(uint32_t* r, uint32_t addr) {
    asm volatile("ldmatrix.sync.aligned.m8n8.x4.shared.b16 {%0,%1,%2,%3}, [%4];"
                 : "=r"(r[0]), "=r"(r[1]), "=r"(r[2]), "=r"(r[3]) : "r"(addr));
}

__device__ __forceinline__ void mma16816(float* c, const uint32_t* a, uint32_t b0, uint32_t b1) {
    asm volatile("mma.sync.aligned.m16n8k16.row.col.f32.bf16.bf16.f32 "
                 "{%0,%1,%2,%3}, {%4,%5,%6,%7}, {%8,%9}, {%0,%1,%2,%3};"
                 : "+f"(c[0]), "+f"(c[1]), "+f"(c[2]), "+f"(c[3])
                 : "r"(a[0]), "r"(a[1]), "r"(a[2]), "r"(a[3]), "r"(b0), "r"(b1));
}

// ---- bf16 hi/lo split ----
__device__ __forceinline__ void bsplit(float v, __nv_bfloat16& h, __nv_bfloat16& l) {
    h = __float2bfloat16(v);
    l = __float2bfloat16(v - __bfloat162float(h));
}
__device__ __forceinline__ void store4_2seg(__nv_bfloat16* base, size_t o, size_t seg, float4 v) {
    __nv_bfloat16 h0,l0,h1,l1,h2,l2,h3,l3;
    bsplit(v.x,h0,l0); bsplit(v.y,h1,l1); bsplit(v.z,h2,l2); bsplit(v.w,h3,l3);
    __nv_bfloat162 ha; ha.x=h0; ha.y=h1;
    __nv_bfloat162 hb; hb.x=h2; hb.y=h3;
    __nv_bfloat162 la; la.x=l0; la.y=l1;
    __nv_bfloat162 lb; lb.x=l2; lb.y=l3;
    *reinterpret_cast<__nv_bfloat162*>(base + o)           = ha;
    *reinterpret_cast<__nv_bfloat162*>(base + o + 2)       = hb;
    *reinterpret_cast<__nv_bfloat162*>(base + o + seg)     = la;
    *reinterpret_cast<__nv_bfloat162*>(base + o + seg + 2) = lb;
}

// ======================= launch 1: weight conversion + counter init =======================
#define CONV13_BLOCKS 5472   // NE*H*D/4/256
#define CONV2_BLOCKS  5632   // NE*D*176/256
__global__ void k_conv(const float* __restrict__ w1, const float* __restrict__ w3,
                       const float* __restrict__ w2) {
    int bx = blockIdx.x;
    if (bx == 0 && threadIdx.x < NE) {
        g_cnt[threadIdx.x] = 0; g_cur[threadIdx.x] = 0;
        g_dcnt[threadIdx.x] = 0; g_psum[threadIdx.x] = 0.f;
    }
    if (bx < CONV13_BLOCKS) {
        size_t i = (size_t)bx * 256 + threadIdx.x;
        size_t row = i >> 8;
        size_t col = (i & 255) * 4;
        float4 a = reinterpret_cast<const float4*>(w1)[i];
        float4 b = reinterpret_cast<const float4*>(w3)[i];
        store4_2seg(w1c, row * KA1 + col, D_DIM, a);
        store4_2seg(w3c, row * KA1 + col, D_DIM, b);
    } else {
        size_t i = (size_t)(bx - CONV13_BLOCKS) * 256 + threadIdx.x;
        size_t row = i / 176;
        int col = (int)(i % 176) * 4;
        float4 v = make_float4(0.f, 0.f, 0.f, 0.f);
        if (col < H_DIM) {
            const float* p = w2 + row * H_DIM + col;
            v.x = p[0];
            v.y = (col + 1 < H_DIM) ? p[1] : 0.f;
            v.z = (col + 2 < H_DIM) ? p[2] : 0.f;
            v.w = (col + 3 < H_DIM) ? p[3] : 0.f;
        }
        store4_2seg(w2c, row * KA2 + (size_t)col, HP, v);
    }
}

// ======================= launch 2: router =======================
__global__ void k_router(const float* __restrict__ x, const float* __restrict__ rw) {
    __shared__ float s_ps[NE];
    __shared__ int   s_dc[NE];
    __shared__ int   s_cnt[NE];
    int tid = threadIdx.x;
    if (tid < NE) { s_ps[tid] = 0.f; s_dc[tid] = 0; s_cnt[tid] = 0; }
    __syncthreads();

    int warp = tid >> 5, lane = tid & 31;
    int t = blockIdx.x * 8 + warp;

    float xv[32];
    const float* xr = x + (size_t)t * D_DIM;
#pragma unroll
    for (int i = 0; i < 32; i++) xv[i] = xr[lane + 32 * i];

    float logit[NE];
#pragma unroll
    for (int e = 0; e < NE; e++) {
        const float* wr = rw + e * D_DIM;
        float s = 0.f;
#pragma unroll
        for (int i = 0; i < 32; i++) s += xv[i] * wr[lane + 32 * i];
#pragma unroll
        for (int o = 16; o; o >>= 1) s += __shfl_xor_sync(0xffffffffu, s, o);
        logit[e] = s;
    }

    if (lane == 0) {
        float mx = logit[0];
#pragma unroll
        for (int e = 1; e < NE; e++) mx = fmaxf(mx, logit[e]);
        float p[NE], sum = 0.f;
#pragma unroll
        for (int e = 0; e < NE; e++) { p[e] = expf(logit[e] - mx); sum += p[e]; }
        float inv = 1.f / sum;
#pragma unroll
        for (int e = 0; e < NE; e++) p[e] *= inv;

        int i0 = 0;
#pragma unroll
        for (int e = 1; e < NE; e++) if (p[e] > p[i0]) i0 = e;
        int i1 = (i0 == 0) ? 1 : 0;
#pragma unroll
        for (int e = 0; e < NE; e++) if (e != i0 && p[e] > p[i1]) i1 = e;

        g_top[t * 2]      = i0;    g_top[t * 2 + 1]  = i1;
        g_topp[t * 2]     = p[i0]; g_topp[t * 2 + 1] = p[i1];

        atomicAdd(&s_dc[i0], 1);
        atomicAdd(&s_cnt[i0], 1);
        atomicAdd(&s_cnt[i1], 1);
#pragma unroll
        for (int e = 0; e < NE; e++) atomicAdd(&s_ps[e], p[e]);
    }
    __syncthreads();
    if (tid < NE) {
        atomicAdd(&g_psum[tid], s_ps[tid]);
        atomicAdd(&g_dcnt[tid], s_dc[tid]);
        atomicAdd(&g_cnt[tid], s_cnt[tid]);
    }
}

// ======================= launch 3: scatter + gather/split + aux =======================
// one warp per slot; position via atomic cursor; copies x row into xg2 [hi|lo]
__global__ void k_scatgather(const float* __restrict__ x, float* __restrict__ out, int out_size) {
    int wid = threadIdx.x >> 5, lane = threadIdx.x & 31;
    int i = blockIdx.x * 8 + wid;            // slot id (2048 blocks * 8 warps = TT)

    if (blockIdx.x == 0 && threadIdx.x == 0) {
        float s = 0.f;
        for (int e = 0; e < NE; e++)
            s += ((float)g_dcnt[e] / (float)T_TOK) * (g_psum[e] / (float)T_TOK);
        if (out_size > T_TOK * D_DIM) out[T_TOK * D_DIM] = 0.01f * s * (float)NE;
    }

    int e = g_top[i];
    int pos = 0;
    if (lane == 0) {
        int o = 0;
        for (int k = 0; k < NE; k++) { if (k == e) break; o += g_cnt[k]; }
        pos = o + atomicAdd(&g_cur[e], 1);
        g_pos[i] = pos;
    }
    pos = __shfl_sync(0xffffffffu, pos, 0);

    int tok = i >> 1;
    const float4* xr = reinterpret_cast<const float4*>(x) + (size_t)tok * 256;
#pragma unroll
    for (int j = 0; j < 8; j++) {
        int c = lane + j * 32;
        store4_2seg(xg2, (size_t)pos * KA1 + (size_t)c * 4, D_DIM, xr[c]);
    }
}

// ======================= per-expert tile base: offsets from g_cnt =======================
__device__ __forceinline__ int expert_base(int e) {
    int o = 0;
    for (int k = 0; k < e; k++) o += g_cnt[k];
    return o;
}

// ======================= GEMM cores =======================
#define TILE_B   10240     // 128 rows * 80B
#define RSTRIDE  80
#define STAGE1   (6 * TILE_B)   // Ah Al B1h B1l B3h B3l
#define STAGE2   (4 * TILE_B)   // Ah Al Bh Bl

__device__ __forceinline__ void compute_warp(
    uint32_t sB, const uint32_t a[2][2][4],
    float acc[2][4][4], int warp_n0, int lane)
{
#pragma unroll
    for (int nj2 = 0; nj2 < 2; nj2++) {
#pragma unroll
        for (int kh = 0; kh < 2; kh++) {
            uint32_t r[4];
            uint32_t bd = sB + (warp_n0 + nj2*16 + (lane & 15)) * RSTRIDE
                             + (kh*16 + (lane >> 4) * 8) * 2;
            ldsm4(r, bd);
            mma16816(acc[0][nj2*2 + 0], a[0][kh], r[0], r[2]);
            mma16816(acc[0][nj2*2 + 1], a[0][kh], r[1], r[3]);
            mma16816(acc[1][nj2*2 + 0], a[1][kh], r[0], r[2]);
            mma16816(acc[1][nj2*2 + 1], a[1][kh], r[1], r[3]);
        }
    }
}

__device__ __forceinline__ void load_a_frags(
    uint32_t sA, uint32_t a[2][2][4], int warp_m0, int lane)
{
#pragma unroll
    for (int mi = 0; mi < 2; mi++)
#pragma unroll
        for (int kh = 0; kh < 2; kh++) {
            uint32_t ad = sA + (warp_m0 + mi*16 + (lane & 15)) * RSTRIDE
                             + (kh*16 + (lane >> 4) * 8) * 2;
            ldsm4(a[mi][kh], ad);
        }
}

// ------- launch 4 (PROFILED): GEMM1, 128x128 CTA, term-fused -------
__global__ __launch_bounds__(512, 1) void k_gemm1() {
    extern __shared__ char smem[];
    const int e = blockIdx.z;
    const int cnt = g_cnt[e];
    const int m0 = blockIdx.x * 128;
    if (m0 >= cnt) return;
    const int base = expert_base(e);
    const int n0g = blockIdx.y * 128;
    const int tid = threadIdx.x, wid = tid >> 5, lane = tid & 31;
    const int warp_m0 = (wid >> 2) * 32, warp_n0 = (wid & 3) * 32;

    uint32_t sb = smem_to_u32(smem);
    const __nv_bfloat16* B1 = w1c + (size_t)e * H_DIM * KA1;
    const __nv_bfloat16* B3 = w3c + (size_t)e * H_DIM * KA1;
    const long arow = base + m0;
    const int lrow = tid >> 2, lch = tid & 3;

    long ar = arow + lrow; if (ar >= TT) ar = TT - 1;
    int nr = n0g + lrow;  if (nr > H_DIM - 1) nr = H_DIM - 1;
    const __nv_bfloat16* gAh  = xg2 + ar * (long)KA1 + lch * 8;
    const __nv_bfloat16* gB1h = B1 + (long)nr * KA1 + lch * 8;
    const __nv_bfloat16* gB3h = B3 + (long)nr * KA1 + lch * 8;
    const uint32_t sdst = sb + lrow * RSTRIDE + lch * 16;

    auto load_stage = [&](int st, int kc) {
        uint32_t d = sdst + st * STAGE1;
        int ko = kc * 32;
        cp16(d,            gAh  + ko);
        cp16(d + TILE_B,   gAh  + D_DIM + ko);
        cp16(d + 2*TILE_B, gB1h + ko);
        cp16(d + 3*TILE_B, gB1h + D_DIM + ko);
        cp16(d + 4*TILE_B, gB3h + ko);
        cp16(d + 5*TILE_B, gB3h + D_DIM + ko);
    };

    float acc1[2][4][4] = {{{0}}}, acc3[2][4][4] = {{{0}}};

    load_stage(0, 0); CP_COMMIT();
    load_stage(1, 1); CP_COMMIT();

    for (int kc = 0; kc < NCH1; kc++) {
        CP_WAIT1();
        __syncthreads();
        if (kc + 2 < NCH1) load_stage((kc + 2) % 3, kc + 2);
        CP_COMMIT();
        uint32_t st = sb + (kc % 3) * STAGE1;
        uint32_t a[2][2][4];
        load_a_frags(st, a, warp_m0, lane);                 // Ah
        compute_warp(st + 2*TILE_B, a, acc1, warp_n0, lane); // Ah*B1h
        compute_warp(st + 3*TILE_B, a, acc1, warp_n0, lane); // Ah*B1l
        compute_warp(st + 4*TILE_B, a, acc3, warp_n0, lane); // Ah*B3h
        compute_warp(st + 5*TILE_B, a, acc3, warp_n0, lane); // Ah*B3l
        load_a_frags(st + TILE_B, a, warp_m0, lane);        // Al
        compute_warp(st + 2*TILE_B, a, acc1, warp_n0, lane); // Al*B1h
        compute_warp(st + 4*TILE_B, a, acc3, warp_n0, lane); // Al*B3h
    }

    // epilogue: swiglu + split into h2 [hi | lo]
#pragma unroll
    for (int mi = 0; mi < 2; mi++) {
#pragma unroll
        for (int nj = 0; nj < 4; nj++) {
            int n = n0g + warp_n0 + nj * 8 + ((lane & 3) << 1);
            if (n >= HP) continue;
            bool live = (n < H_DIM);
#pragma unroll
            for (int h = 0; h < 2; h++) {
                int rl = warp_m0 + mi * 16 + (lane >> 2) + h * 8;
                int r = m0 + rl;
                if (r >= cnt) continue;
                float v1a = acc1[mi][nj][2*h],   v3a = acc3[mi][nj][2*h];
                float v1b = acc1[mi][nj][2*h+1], v3b = acc3[mi][nj][2*h+1];
                float ha = live ? (v1a / (1.f + __expf(-v1a))) * v3a : 0.f;
                float hb = live ? (v1b / (1.f + __expf(-v1b))) * v3b : 0.f;
                __nv_bfloat16 hah, hal, hbh, hbl;
                bsplit(ha, hah, hal); bsplit(hb, hbh, hbl);
                __nv_bfloat162 hv; hv.x = hah; hv.y = hbh;
                __nv_bfloat162 lv; lv.x = hal; lv.y = hbl;
                size_t rb = (size_t)(base + r) * KA2;
                *reinterpret_cast<__nv_bfloat162*>(h2_ + rb + n)      = hv;
                *reinterpret_cast<__nv_bfloat162*>(h2_ + rb + HP + n) = lv;
            }
        }
    }
}

// ------- launch 5: GEMM2, 128x128 CTA, term-fused, 4-stage -------
__global__ __launch_bounds__(512, 1) void k_gemm2() {
    extern __shared__ char smem[];
    const int e = blockIdx.z;
    const int cnt = g_cnt[e];
    const int m0 = blockIdx.x * 128;
    if (m0 >= cnt) return;
    const int base = expert_base(e);
    const int n0g = blockIdx.y * 128;
    const int tid = threadIdx.x, wid = tid >> 5, lane = tid & 31;
    const int warp_m0 = (wid >> 2) * 32, warp_n0 = (wid & 3) * 32;

    uint32_t sb = smem_to_u32(smem);
    const __nv_bfloat16* B = w2c + (size_t)e * D_DIM * KA2;
    const long arow = base + m0;
    const int lrow = tid >> 2, lch = tid & 3;

    long ar = arow + lrow; if (ar >= TT) ar = TT - 1;
    int nr = n0g + lrow;                       // < 1024 always
    const __nv_bfloat16* gAh = h2_ + ar * (long)KA2 + lch * 8;
    const __nv_bfloat16* gBh = B + (long)nr * KA2 + lch * 8;
    const uint32_t sdst = sb + lrow * RSTRIDE + lch * 16;

    auto load_stage = [&](int st, int kc) {
        uint32_t d = sdst + st * STAGE2;
        int ko = kc * 32;
        cp16(d,            gAh + ko);
        cp16(d + TILE_B,   gAh + HP + ko);
        cp16(d + 2*TILE_B, gBh + ko);
        cp16(d + 3*TILE_B, gBh + HP + ko);
    };

    float acc[2][4][4] = {{{0}}};

    load_stage(0, 0); CP_COMMIT();
    load_stage(1, 1); CP_COMMIT();
    load_stage(2, 2); CP_COMMIT();

    for (int kc = 0; kc < NCH2; kc++) {
        CP_WAIT2();
        __syncthreads();
        if (kc + 3 < NCH2) load_stage((kc + 3) & 3, kc + 3);
        CP_COMMIT();
        uint32_t st = sb + (kc & 3) * STAGE2;
        uint32_t a[2][2][4];
        load_a_frags(st, a, warp_m0, lane);                 // Ah
        compute_warp(st + 2*TILE_B, a, acc, warp_n0, lane);  // Ah*Bh
        compute_warp(st + 3*TILE_B, a, acc, warp_n0, lane);  // Ah*Bl
        load_a_frags(st + TILE_B, a, warp_m0, lane);        // Al
        compute_warp(st + 2*TILE_B, a, acc, warp_n0, lane);  // Al*Bh
    }

#pragma unroll
    for (int mi = 0; mi < 2; mi++) {
#pragma unroll
        for (int nj = 0; nj < 4; nj++) {
            int n = n0g + warp_n0 + nj * 8 + ((lane & 3) << 1);
#pragma unroll
            for (int h = 0; h < 2; h++) {
                int rl = warp_m0 + mi * 16 + (lane >> 2) + h * 8;
                int r = m0 + rl;
                if (r >= cnt) continue;
                float2 v; v.x = acc[mi][nj][2*h]; v.y = acc[mi][nj][2*h+1];
                *reinterpret_cast<float2*>(g_y + (size_t)(base + r) * D_DIM + n) = v;
            }
        }
    }
}

// ======================= launch 6: combine =======================
__global__ void k_combine(float* __restrict__ out) {
    int i = blockIdx.x * 256 + threadIdx.x;
    int t = i >> 8, c = i & 255;
    int p0 = g_pos[2 * t], p1 = g_pos[2 * t + 1];
    float c0 = g_topp[2 * t], c1 = g_topp[2 * t + 1];
    const float4* y = reinterpret_cast<const float4*>(g_y);
    float4 a = y[(size_t)p0 * 256 + c];
    float4 b = y[(size_t)p1 * 256 + c];
    float4 o;
    o.x = c0 * a.x + c1 * b.x;  o.y = c0 * a.y + c1 * b.y;
    o.z = c0 * a.z + c1 * b.z;  o.w = c0 * a.w + c1 * b.w;
    reinterpret_cast<float4*>(out)[(size_t)t * 256 + c] = o;
}

// ======================= launch =======================
extern "C" void kernel_launch(void* const* d_in, const int* in_sizes, int n_in,
                              void* d_out, int out_size) {
    const float* x  = (const float*)d_in[0];
    const float* rw = (const float*)d_in[1];
    const float* w1 = (const float*)d_in[2];
    const float* w2 = (const float*)d_in[3];
    const float* w3 = (const float*)d_in[4];
    float* out = (float*)d_out;

    cudaFuncSetAttribute(k_gemm1, cudaFuncAttributeMaxDynamicSharedMemorySize, 3 * STAGE1);
    cudaFuncSetAttribute(k_gemm2, cudaFuncAttributeMaxDynamicSharedMemorySize, 4 * STAGE2);

    k_conv<<<CONV13_BLOCKS + CONV2_BLOCKS, 256>>>(w1, w3, w2);   // #1
    k_router<<<T_TOK / 8, 256>>>(x, rw);                          // #2
    k_scatgather<<<TT / 8, 256>>>(x, out, out_size);              // #3
    k_gemm1<<<dim3(64, 6, 8), 512, 3 * STAGE1>>>();               // #4 <- profiled
    k_gemm2<<<dim3(64, 8, 8), 512, 4 * STAGE2>>>();               // #5
    k_combine<<<T_TOK, 256>>>(out);                               // #6
}